// round 12
// baseline (speedup 1.0000x reference)
#include <cuda_runtime.h>
#include <cstdint>

// ---------------------------------------------------------------------------
// Problem constants
// ---------------------------------------------------------------------------
#define TREE_DEPTH 13
#define N_NODES 8191
#define MAX_LEN 16381
#define DM 256
#define KMSG 768
#define TOK 2048                  // 8 * 256 floats per token
#define MTOT (MAX_LEN * 8)        // 131048 projection rows
#define N_INTERNAL 4095
#define RS 36                     // smem row stride in floats (bank-conflict-free)

__device__ float g_xs[(size_t)N_INTERNAL * TOK];   // internal-node x scratch (33.5 MB)
__device__ float g_wlin[DM * DM];                  // rna-tf32 Wlin
__device__ float g_wmsg[DM * KMSG];                // rna-tf32 Wmsg

// ---------------------------------------------------------------------------
// Helpers
// ---------------------------------------------------------------------------
__device__ __forceinline__ uint32_t f2tf(float x) {
    uint32_t r;
    asm("cvt.rna.tf32.f32 %0, %1;" : "=r"(r) : "f"(x));
    return r;
}

__device__ __forceinline__ void cp16(uint32_t dst, const void* src) {
    asm volatile("cp.async.cg.shared.global [%0], [%1], 16;" :: "r"(dst), "l"(src) : "memory");
}
__device__ __forceinline__ void cp_commit() {
    asm volatile("cp.async.commit_group;" ::: "memory");
}
template<int N> __device__ __forceinline__ void cp_wait() {
    asm volatile("cp.async.wait_group %0;" :: "n"(N) : "memory");
}

__device__ __forceinline__ void mma_tf32(float& c0, float& c1, float& c2, float& c3,
                                         uint32_t a0, uint32_t a1, uint32_t a2, uint32_t a3,
                                         uint32_t b0, uint32_t b1) {
    asm volatile(
        "mma.sync.aligned.m16n8k8.row.col.f32.tf32.tf32.f32 "
        "{%0,%1,%2,%3}, {%4,%5,%6,%7}, {%8,%9}, {%0,%1,%2,%3};"
        : "+f"(c0), "+f"(c1), "+f"(c2), "+f"(c3)
        : "r"(a0), "r"(a1), "r"(a2), "r"(a3), "r"(b0), "r"(b1));
}

// ---------------------------------------------------------------------------
// Weight pre-conversion to rna-tf32 (stored as fp32 bit pattern)
// ---------------------------------------------------------------------------
__global__ void prep_w_kernel(const float* __restrict__ Wlin, const float* __restrict__ Wmsg)
{
    int i = blockIdx.x * blockDim.x + threadIdx.x;
    if (i < DM * DM)   g_wlin[i] = __uint_as_float(f2tf(Wlin[i]));
    if (i < DM * KMSG) g_wmsg[i] = __uint_as_float(f2tf(Wmsg[i]));
}

// ---------------------------------------------------------------------------
// Unified GEMM kernel (cp.async multistage, mma.sync tf32, single-sync loop).
//  LEVEL=false: dst[r,:] = Aproj[r,:] @ Wlin^T          (proj)
//  LEVEL=true : row g: q=g>>4, j=g&15, s=j>>3, b=j&7, p=pbase+q, c=2p+1+s
//               A row g = concat(x[c], x[p], e[c-1]); C pairs (gid, gid+8)
//               share (q,b), differ in s -> min in-thread; write g_xs[p].
// BM==BN; WNW warps along N; NTHR/32 warps total.
// ---------------------------------------------------------------------------
template<int BM, int BN, int NTHR, int WNW, int STAGES, bool LEVEL>
__global__ __launch_bounds__(NTHR, (BM == 128 ? 2 : 3))
void gemm_k(const float* __restrict__ Aproj,   // proj: feats (unused for LEVEL)
            float* __restrict__ outBuf,        // proj: dst; LEVEL: x_parent/e (+child at top)
            int M, int K, int pbase, int childFromOut)
{
    constexpr int MW = (NTHR / 32) / WNW;        // warps along M
    constexpr int MT = BM / (16 * MW);           // 16-row mtiles per warp
    constexpr int NT = BN / (8 * WNW);           // 8-col ntiles per warp
    constexpr int STG_FLT = (BM + BN) * RS;      // floats per stage
    constexpr int TPR = NTHR / BM;               // loader threads per row (1 or 2)
    constexpr int FPT = 32 / TPR;                // floats loaded per thread per row
    extern __shared__ float sm[];
    const uint32_t smBase = (uint32_t)__cvta_generic_to_shared(sm);

    const int tid = threadIdx.x, lane = tid & 31, wid = tid >> 5;
    const int gid = lane >> 2, tig = lane & 3;
    const int m0 = (wid / WNW) * (MT * 16);
    const int n0 = (wid % WNW) * (NT * 8);
    const int bn = blockIdx.x;
    const int rowBase = blockIdx.y * BM;

    const float* W = LEVEL ? g_wmsg : g_wlin;

    // ---- loader setup ----
    const int ra = tid / TPR;
    const int coff = (tid % TPR) * FPT;
    const float* asrc[3];
    if (LEVEL) {
        const float* childRO = childFromOut ? (const float*)outBuf : (const float*)g_xs;
        int g = min(rowBase + ra, M - 1);
        int q = g >> 4, j = g & 15, s = j >> 3, b = j & 7;
        int p = pbase + q, c = 2 * p + 1 + s;
        asrc[0] = childRO + (size_t)c * TOK + b * DM;                       // x[child]
        asrc[1] = outBuf + (size_t)p * TOK + b * DM;                        // x[parent]
        asrc[2] = outBuf + (size_t)(N_NODES + c - 1) * TOK + b * DM;        // e[child-1]
    } else {
        int g = min(rowBase + ra, M - 1);
        asrc[0] = asrc[1] = asrc[2] = Aproj + (size_t)g * DM;
    }
    const float* bsrc = W + (size_t)(bn * BN + ra) * K;

    const int nslab = K >> 5;

    auto load_stage = [&](int slab, int buf) {
        int kg = slab << 5;
        const float* a = asrc[kg >> 8] + (kg & 255) + coff;
        const float* b = bsrc + kg + coff;
        uint32_t da = smBase + (uint32_t)(buf * STG_FLT + ra * RS + coff) * 4u;
        uint32_t db = smBase + (uint32_t)(buf * STG_FLT + BM * RS + ra * RS + coff) * 4u;
#pragma unroll
        for (int i = 0; i < FPT / 4; i++) { cp16(da + i * 16, a + i * 4); cp16(db + i * 16, b + i * 4); }
        cp_commit();
    };

#pragma unroll
    for (int s = 0; s < STAGES - 1; s++) load_stage(s, s);

    float acc[MT][NT][4];
#pragma unroll
    for (int mt = 0; mt < MT; mt++)
#pragma unroll
        for (int nt = 0; nt < NT; nt++)
#pragma unroll
            for (int c = 0; c < 4; c++) acc[mt][nt][c] = 0.f;

    for (int s = 0; s < nslab; s++) {
        cp_wait<STAGES - 2>();
        __syncthreads();
        // Refill buffer (s-1)%STAGES: consumed in iter s-1, all warps are past it.
        int nx = s + STAGES - 1;
        if (nx < nslab) load_stage(nx, nx % STAGES);
        else cp_commit();

        const uint32_t* As = (const uint32_t*)sm + (s % STAGES) * STG_FLT;
        const uint32_t* Bs = As + BM * RS;
#pragma unroll
        for (int k8 = 0; k8 < 4; k8++) {
            const int kb = k8 * 8;
            uint32_t a[MT][4];
#pragma unroll
            for (int mt = 0; mt < MT; mt++) {
                int r0 = (m0 + mt * 16 + gid) * RS + kb + tig;
                a[mt][0] = As[r0];
                a[mt][1] = As[r0 + 8 * RS];
                a[mt][2] = As[r0 + 4];
                a[mt][3] = As[r0 + 8 * RS + 4];
            }
            uint32_t b[NT][2];
#pragma unroll
            for (int nt = 0; nt < NT; nt++) {
                int rb = (n0 + nt * 8 + gid) * RS + kb + tig;
                b[nt][0] = Bs[rb];
                b[nt][1] = Bs[rb + 4];
            }
#pragma unroll
            for (int mt = 0; mt < MT; mt++)
#pragma unroll
                for (int nt = 0; nt < NT; nt++)
                    mma_tf32(acc[mt][nt][0], acc[mt][nt][1], acc[mt][nt][2], acc[mt][nt][3],
                             a[mt][0], a[mt][1], a[mt][2], a[mt][3], b[nt][0], b[nt][1]);
        }
    }

    // ---- epilogue ----
    if (!LEVEL) {
#pragma unroll
        for (int mt = 0; mt < MT; mt++) {
            int r = rowBase + m0 + mt * 16 + gid;
#pragma unroll
            for (int nt = 0; nt < NT; nt++) {
                int ncol = bn * BN + n0 + nt * 8 + 2 * tig;
                if (r < M)
                    *(float2*)(outBuf + (size_t)r * DM + ncol) =
                        make_float2(acc[mt][nt][0], acc[mt][nt][1]);
                if (r + 8 < M)
                    *(float2*)(outBuf + (size_t)(r + 8) * DM + ncol) =
                        make_float2(acc[mt][nt][2], acc[mt][nt][3]);
            }
        }
    } else {
#pragma unroll
        for (int mt = 0; mt < MT; mt++) {
            int r = rowBase + m0 + mt * 16 + gid;   // s=0 row (r&15 = gid < 8)
            if (r < M) {
                int p = pbase + (r >> 4), b = r & 7;
                float* o = g_xs + (size_t)p * TOK + b * DM + bn * BN + n0 + 2 * tig;
#pragma unroll
                for (int nt = 0; nt < NT; nt++)
                    *(float2*)(o + nt * 8) =
                        make_float2(fminf(acc[mt][nt][0], acc[mt][nt][2]),
                                    fminf(acc[mt][nt][1], acc[mt][nt][3]));
            }
        }
    }
}

// ---------------------------------------------------------------------------
// Final merge: internal-node x scratch -> d_out
// ---------------------------------------------------------------------------
__global__ __launch_bounds__(256) void merge_kernel(float* __restrict__ out)
{
    size_t idx = (size_t)blockIdx.x * blockDim.x + threadIdx.x;
    const size_t n4 = (size_t)N_INTERNAL * TOK / 4;
    if (idx < n4) ((float4*)out)[idx] = ((const float4*)g_xs)[idx];
}

// ---------------------------------------------------------------------------
#define SMEM_BIG   (3 * (128 + 128) * RS * 4)   // 110592 B
#define SMEM_SMALL (4 * (64 + 64) * RS * 4)     //  73728 B

// Big kernels: 128 threads, 4 warps of 64x64 (MT=4, NT=8) -> LDS/mma = 1.0
// Small kernel: 128 threads, 4 warps of 32x32 over 64x64 tile (latency-bound levels)

extern "C" void kernel_launch(void* const* d_in, const int* in_sizes, int n_in,
                              void* d_out, int out_size)
{
    const float* feats = (const float*)d_in[0];
    const float* Wlin  = (const float*)d_in[1];
    const float* Wmsg  = (const float*)d_in[2];
    float* out = (float*)d_out;

    (void)cudaFuncSetAttribute((const void*)gemm_k<128, 128, 128, 2, 3, false>,
                               cudaFuncAttributeMaxDynamicSharedMemorySize, SMEM_BIG);
    (void)cudaFuncSetAttribute((const void*)gemm_k<128, 128, 128, 2, 3, true>,
                               cudaFuncAttributeMaxDynamicSharedMemorySize, SMEM_BIG);
    (void)cudaFuncSetAttribute((const void*)gemm_k<64, 64, 128, 2, 4, true>,
                               cudaFuncAttributeMaxDynamicSharedMemorySize, SMEM_SMALL);

    // 1) weights -> rna tf32
    prep_w_kernel<<<(DM * KMSG + 255) / 256, 256>>>(Wlin, Wmsg);

    // 2) projection: out = feats @ Wlin^T
    {
        dim3 grid(DM / 128, (MTOT + 127) / 128);   // (2, 1024)
        gemm_k<128, 128, 128, 2, 3, false><<<grid, 128, SMEM_BIG>>>(
            feats, out, MTOT, DM, 0, 0);
    }

    // 3) tree levels
    for (int d = TREE_DEPTH - 2; d >= 0; --d) {
        int pbase = (1 << d) - 1;
        int pcount = 1 << d;
        int M = pcount * 16;
        int cfo = (d == TREE_DEPTH - 2) ? 1 : 0;
        if (d >= 10) {
            dim3 grid(DM / 128, (M + 127) / 128);
            gemm_k<128, 128, 128, 2, 3, true><<<grid, 128, SMEM_BIG>>>(
                feats, out, M, KMSG, pbase, cfo);
        } else {
            dim3 grid(DM / 64, (M + 63) / 64);
            gemm_k<64, 64, 128, 2, 4, true><<<grid, 128, SMEM_SMALL>>>(
                feats, out, M, KMSG, pbase, cfo);
        }
    }

    // 4) merge internal-node x into d_out
    {
        size_t n4 = (size_t)N_INTERNAL * TOK / 4;
        merge_kernel<<<(int)((n4 + 255) / 256), 256>>>(out);
    }
}

// round 15
// speedup vs baseline: 1.1387x; 1.1387x over previous
#include <cuda_runtime.h>
#include <cstdint>

// ---------------------------------------------------------------------------
// Problem constants
// ---------------------------------------------------------------------------
#define TREE_DEPTH 13
#define N_NODES 8191
#define MAX_LEN 16381
#define DM 256
#define KMSG 768
#define TOK 2048                  // 8 * 256 floats per token
#define MTOT (MAX_LEN * 8)        // 131048 projection rows
#define N_INTERNAL 4095
#define RS 36                     // smem row stride in floats (bank-conflict-free)

__device__ float g_xs[(size_t)N_INTERNAL * TOK];   // internal-node x scratch (33.5 MB)
__device__ float g_wlin[DM * DM];                  // rna-tf32 Wlin
__device__ float g_wmsg[DM * KMSG];                // rna-tf32 Wmsg

// ---------------------------------------------------------------------------
// Helpers
// ---------------------------------------------------------------------------
__device__ __forceinline__ uint32_t f2tf(float x) {
    uint32_t r;
    asm("cvt.rna.tf32.f32 %0, %1;" : "=r"(r) : "f"(x));
    return r;
}

__device__ __forceinline__ void cp16(uint32_t dst, const void* src) {
    asm volatile("cp.async.cg.shared.global [%0], [%1], 16;" :: "r"(dst), "l"(src) : "memory");
}
__device__ __forceinline__ void cp_commit() {
    asm volatile("cp.async.commit_group;" ::: "memory");
}
template<int N> __device__ __forceinline__ void cp_wait() {
    asm volatile("cp.async.wait_group %0;" :: "n"(N) : "memory");
}

__device__ __forceinline__ void ldsm_x4(uint32_t& r0, uint32_t& r1, uint32_t& r2, uint32_t& r3,
                                        uint32_t addr) {
    asm volatile("ldmatrix.sync.aligned.m8n8.x4.shared.b16 {%0,%1,%2,%3}, [%4];"
                 : "=r"(r0), "=r"(r1), "=r"(r2), "=r"(r3) : "r"(addr));
}
__device__ __forceinline__ void ldsm_x2(uint32_t& r0, uint32_t& r1, uint32_t addr) {
    asm volatile("ldmatrix.sync.aligned.m8n8.x2.shared.b16 {%0,%1}, [%2];"
                 : "=r"(r0), "=r"(r1) : "r"(addr));
}

__device__ __forceinline__ void mma_tf32(float& c0, float& c1, float& c2, float& c3,
                                         uint32_t a0, uint32_t a1, uint32_t a2, uint32_t a3,
                                         uint32_t b0, uint32_t b1) {
    asm volatile(
        "mma.sync.aligned.m16n8k8.row.col.f32.tf32.tf32.f32 "
        "{%0,%1,%2,%3}, {%4,%5,%6,%7}, {%8,%9}, {%0,%1,%2,%3};"
        : "+f"(c0), "+f"(c1), "+f"(c2), "+f"(c3)
        : "r"(a0), "r"(a1), "r"(a2), "r"(a3), "r"(b0), "r"(b1));
}

// ---------------------------------------------------------------------------
// Weight pre-conversion to rna-tf32 (stored as fp32 bit pattern)
// ---------------------------------------------------------------------------
__global__ void prep_w_kernel(const float* __restrict__ Wlin, const float* __restrict__ Wmsg)
{
    int i = blockIdx.x * blockDim.x + threadIdx.x;
    if (i < DM * DM)   g_wlin[i] = __uint_as_float(f2tf(Wlin[i]));
    if (i < DM * KMSG) g_wmsg[i] = __uint_as_float(f2tf(Wmsg[i]));
}

// ---------------------------------------------------------------------------
// Unified GEMM kernel (cp.async multistage, ldmatrix feeds, mma.sync tf32).
//  LEVEL=false: dst[r,:] = Aproj[r,:] @ Wlin^T          (proj)
//  LEVEL=true : row g: q=g>>4, j=g&15, s=j>>3, b=j&7, p=pbase+q, c=2p+1+s
//               A row g = concat(x[c], x[p], e[c-1]); C pairs (gid, gid+8)
//               share (q,b), differ in s -> min in-thread; write g_xs[p].
// BM==BN; WNW warps along N; NTHR/32 warps total.
// ---------------------------------------------------------------------------
template<int BM, int BN, int NTHR, int WNW, int STAGES, bool LEVEL>
__global__ __launch_bounds__(NTHR, (BM == 128 ? 2 : 3))
void gemm_k(const float* __restrict__ Aproj,   // proj: feats (unused for LEVEL)
            float* __restrict__ outBuf,        // proj: dst; LEVEL: x_parent/e (+child at top)
            int M, int K, int pbase, int childFromOut)
{
    constexpr int MW = (NTHR / 32) / WNW;        // warps along M
    constexpr int MT = BM / (16 * MW);           // 16-row mtiles per warp
    constexpr int NT = BN / (8 * WNW);           // 8-col ntiles per warp
    constexpr int STG_FLT = (BM + BN) * RS;      // floats per stage
    constexpr int TPR = NTHR / BM;               // loader threads per row
    constexpr int FPT = 32 / TPR;                // floats loaded per thread per row
    extern __shared__ float sm[];
    const uint32_t smBase = (uint32_t)__cvta_generic_to_shared(sm);

    const int tid = threadIdx.x, lane = tid & 31, wid = tid >> 5;
    const int gid = lane >> 2, tig = lane & 3;
    const int m0 = (wid / WNW) * (MT * 16);
    const int n0 = (wid % WNW) * (NT * 8);
    const int bn = blockIdx.x;
    const int rowBase = blockIdx.y * BM;

    // ldmatrix lane addressing
    const int laneRowA = (lane & 7) + (lane & 8);        // 0..15 pattern for x4
    const int colA4 = ((lane >> 4) & 1) * 4;             // +4 floats for lanes 16..31
    const int laneRowB = lane & 7;
    const int colB4 = ((lane >> 3) & 1) * 4;             // lanes 0..15 meaningful for x2

    const float* W = LEVEL ? g_wmsg : g_wlin;

    // ---- loader setup ----
    const int ra = tid / TPR;
    const int coff = (tid % TPR) * FPT;
    const float* asrc[3];
    if (LEVEL) {
        const float* childRO = childFromOut ? (const float*)outBuf : (const float*)g_xs;
        int g = min(rowBase + ra, M - 1);
        int q = g >> 4, j = g & 15, s = j >> 3, b = j & 7;
        int p = pbase + q, c = 2 * p + 1 + s;
        asrc[0] = childRO + (size_t)c * TOK + b * DM;                       // x[child]
        asrc[1] = outBuf + (size_t)p * TOK + b * DM;                        // x[parent]
        asrc[2] = outBuf + (size_t)(N_NODES + c - 1) * TOK + b * DM;        // e[child-1]
    } else {
        int g = min(rowBase + ra, M - 1);
        asrc[0] = asrc[1] = asrc[2] = Aproj + (size_t)g * DM;
    }
    const float* bsrc = W + (size_t)(bn * BN + ra) * K;

    const int nslab = K >> 5;

    auto load_stage = [&](int slab, int buf) {
        int kg = slab << 5;
        const float* a = asrc[kg >> 8] + (kg & 255) + coff;
        const float* b = bsrc + kg + coff;
        uint32_t da = smBase + (uint32_t)(buf * STG_FLT + ra * RS + coff) * 4u;
        uint32_t db = smBase + (uint32_t)(buf * STG_FLT + BM * RS + ra * RS + coff) * 4u;
#pragma unroll
        for (int i = 0; i < FPT / 4; i++) { cp16(da + i * 16, a + i * 4); cp16(db + i * 16, b + i * 4); }
        cp_commit();
    };

#pragma unroll
    for (int s = 0; s < STAGES - 1; s++) load_stage(s, s);

    float acc[MT][NT][4];
#pragma unroll
    for (int mt = 0; mt < MT; mt++)
#pragma unroll
        for (int nt = 0; nt < NT; nt++)
#pragma unroll
            for (int c = 0; c < 4; c++) acc[mt][nt][c] = 0.f;

    for (int s = 0; s < nslab; s++) {
        cp_wait<STAGES - 2>();
        __syncthreads();
        // Refill buffer (s-1)%STAGES: consumed in iter s-1, all warps are past it.
        int nx = s + STAGES - 1;
        if (nx < nslab) load_stage(nx, nx % STAGES);
        else cp_commit();

        const uint32_t stB = smBase + (uint32_t)((s % STAGES) * STG_FLT) * 4u;
        const uint32_t aBase = stB + (uint32_t)((m0 + laneRowA) * RS + colA4) * 4u;
        const uint32_t bBase = stB + (uint32_t)(BM * RS + (n0 + laneRowB) * RS + colB4) * 4u;
#pragma unroll
        for (int k8 = 0; k8 < 4; k8++) {
            const int kb = k8 * 8;
            uint32_t a[MT][4];
#pragma unroll
            for (int mt = 0; mt < MT; mt++)
                ldsm_x4(a[mt][0], a[mt][1], a[mt][2], a[mt][3],
                        aBase + (uint32_t)((mt * 16 * RS + kb) * 4));
            uint32_t b[NT][2];
#pragma unroll
            for (int nt = 0; nt < NT; nt++)
                ldsm_x2(b[nt][0], b[nt][1],
                        bBase + (uint32_t)((nt * 8 * RS + kb) * 4));
#pragma unroll
            for (int mt = 0; mt < MT; mt++)
#pragma unroll
                for (int nt = 0; nt < NT; nt++)
                    mma_tf32(acc[mt][nt][0], acc[mt][nt][1], acc[mt][nt][2], acc[mt][nt][3],
                             a[mt][0], a[mt][1], a[mt][2], a[mt][3], b[nt][0], b[nt][1]);
        }
    }

    // ---- epilogue ----
    if (!LEVEL) {
#pragma unroll
        for (int mt = 0; mt < MT; mt++) {
            int r = rowBase + m0 + mt * 16 + gid;
#pragma unroll
            for (int nt = 0; nt < NT; nt++) {
                int ncol = bn * BN + n0 + nt * 8 + 2 * tig;
                if (r < M)
                    *(float2*)(outBuf + (size_t)r * DM + ncol) =
                        make_float2(acc[mt][nt][0], acc[mt][nt][1]);
                if (r + 8 < M)
                    *(float2*)(outBuf + (size_t)(r + 8) * DM + ncol) =
                        make_float2(acc[mt][nt][2], acc[mt][nt][3]);
            }
        }
    } else {
#pragma unroll
        for (int mt = 0; mt < MT; mt++) {
            int r = rowBase + m0 + mt * 16 + gid;   // s=0 row (r&15 = gid < 8)
            if (r < M) {
                int p = pbase + (r >> 4), b = r & 7;
                float* o = g_xs + (size_t)p * TOK + b * DM + bn * BN + n0 + 2 * tig;
#pragma unroll
                for (int nt = 0; nt < NT; nt++)
                    *(float2*)(o + nt * 8) =
                        make_float2(fminf(acc[mt][nt][0], acc[mt][nt][2]),
                                    fminf(acc[mt][nt][1], acc[mt][nt][3]));
            }
        }
    }
}

// ---------------------------------------------------------------------------
// Final merge: internal-node x scratch -> d_out
// ---------------------------------------------------------------------------
__global__ __launch_bounds__(256) void merge_kernel(float* __restrict__ out)
{
    size_t idx = (size_t)blockIdx.x * blockDim.x + threadIdx.x;
    const size_t n4 = (size_t)N_INTERNAL * TOK / 4;
    if (idx < n4) ((float4*)out)[idx] = ((const float4*)g_xs)[idx];
}

// ---------------------------------------------------------------------------
#define SMEM_BIG   (3 * (128 + 128) * RS * 4)   // 110592 B
#define SMEM_SMALL (4 * (64 + 64) * RS * 4)     //  73728 B

// Big kernels: 256 threads, 8 warps of 64x32 (MT=4, NT=4), ldmatrix feeds.
// Small kernel: 128 threads, 4 warps of 32x32 over 64x64 tile (latency-bound levels).

extern "C" void kernel_launch(void* const* d_in, const int* in_sizes, int n_in,
                              void* d_out, int out_size)
{
    const float* feats = (const float*)d_in[0];
    const float* Wlin  = (const float*)d_in[1];
    const float* Wmsg  = (const float*)d_in[2];
    float* out = (float*)d_out;

    (void)cudaFuncSetAttribute((const void*)gemm_k<128, 128, 256, 4, 3, false>,
                               cudaFuncAttributeMaxDynamicSharedMemorySize, SMEM_BIG);
    (void)cudaFuncSetAttribute((const void*)gemm_k<128, 128, 256, 4, 3, true>,
                               cudaFuncAttributeMaxDynamicSharedMemorySize, SMEM_BIG);
    (void)cudaFuncSetAttribute((const void*)gemm_k<64, 64, 128, 2, 4, true>,
                               cudaFuncAttributeMaxDynamicSharedMemorySize, SMEM_SMALL);

    // 1) weights -> rna tf32
    prep_w_kernel<<<(DM * KMSG + 255) / 256, 256>>>(Wlin, Wmsg);

    // 2) projection: out = feats @ Wlin^T
    {
        dim3 grid(DM / 128, (MTOT + 127) / 128);   // (2, 1024)
        gemm_k<128, 128, 256, 4, 3, false><<<grid, 256, SMEM_BIG>>>(
            feats, out, MTOT, DM, 0, 0);
    }

    // 3) tree levels
    for (int d = TREE_DEPTH - 2; d >= 0; --d) {
        int pbase = (1 << d) - 1;
        int pcount = 1 << d;
        int M = pcount * 16;
        int cfo = (d == TREE_DEPTH - 2) ? 1 : 0;
        if (d >= 10) {
            dim3 grid(DM / 128, (M + 127) / 128);
            gemm_k<128, 128, 256, 4, 3, true><<<grid, 256, SMEM_BIG>>>(
                feats, out, M, KMSG, pbase, cfo);
        } else {
            dim3 grid(DM / 64, (M + 63) / 64);
            gemm_k<64, 64, 128, 2, 4, true><<<grid, 128, SMEM_SMALL>>>(
                feats, out, M, KMSG, pbase, cfo);
        }
    }

    // 4) merge internal-node x into d_out
    {
        size_t n4 = (size_t)N_INTERNAL * TOK / 4;
        merge_kernel<<<(int)((n4 + 255) / 256), 256>>>(out);
    }
}

// round 16
// speedup vs baseline: 1.1439x; 1.0045x over previous
#include <cuda_runtime.h>
#include <cstdint>

// ---------------------------------------------------------------------------
// Problem constants
// ---------------------------------------------------------------------------
#define TREE_DEPTH 13
#define N_NODES 8191
#define MAX_LEN 16381
#define DM 256
#define KMSG 768
#define TOK 2048                  // 8 * 256 floats per token
#define MTOT (MAX_LEN * 8)        // 131048 projection rows
#define N_INTERNAL 4095
#define RS 36                     // smem row stride in floats (bank-conflict-free)

__device__ float g_xs[(size_t)N_INTERNAL * TOK];   // internal-node x scratch (33.5 MB)
__device__ float g_wlin[DM * DM];                  // rna-tf32 Wlin
__device__ float g_wmsg[DM * KMSG];                // rna-tf32 Wmsg

// ---------------------------------------------------------------------------
// Helpers
// ---------------------------------------------------------------------------
__device__ __forceinline__ uint32_t f2tf(float x) {
    uint32_t r;
    asm("cvt.rna.tf32.f32 %0, %1;" : "=r"(r) : "f"(x));
    return r;
}

__device__ __forceinline__ void cp16(uint32_t dst, const void* src) {
    asm volatile("cp.async.cg.shared.global [%0], [%1], 16;" :: "r"(dst), "l"(src) : "memory");
}
__device__ __forceinline__ void cp_commit() {
    asm volatile("cp.async.commit_group;" ::: "memory");
}
template<int N> __device__ __forceinline__ void cp_wait() {
    asm volatile("cp.async.wait_group %0;" :: "n"(N) : "memory");
}

__device__ __forceinline__ void ldsm_x4(uint32_t& r0, uint32_t& r1, uint32_t& r2, uint32_t& r3,
                                        uint32_t addr) {
    asm volatile("ldmatrix.sync.aligned.m8n8.x4.shared.b16 {%0,%1,%2,%3}, [%4];"
                 : "=r"(r0), "=r"(r1), "=r"(r2), "=r"(r3) : "r"(addr));
}
__device__ __forceinline__ void ldsm_x2(uint32_t& r0, uint32_t& r1, uint32_t addr) {
    asm volatile("ldmatrix.sync.aligned.m8n8.x2.shared.b16 {%0,%1}, [%2];"
                 : "=r"(r0), "=r"(r1) : "r"(addr));
}

__device__ __forceinline__ void mma_tf32(float& c0, float& c1, float& c2, float& c3,
                                         uint32_t a0, uint32_t a1, uint32_t a2, uint32_t a3,
                                         uint32_t b0, uint32_t b1) {
    asm volatile(
        "mma.sync.aligned.m16n8k8.row.col.f32.tf32.tf32.f32 "
        "{%0,%1,%2,%3}, {%4,%5,%6,%7}, {%8,%9}, {%0,%1,%2,%3};"
        : "+f"(c0), "+f"(c1), "+f"(c2), "+f"(c3)
        : "r"(a0), "r"(a1), "r"(a2), "r"(a3), "r"(b0), "r"(b1));
}

// ---------------------------------------------------------------------------
// Weight pre-conversion to rna-tf32 (stored as fp32 bit pattern)
// ---------------------------------------------------------------------------
__global__ void prep_w_kernel(const float* __restrict__ Wlin, const float* __restrict__ Wmsg)
{
    int i = blockIdx.x * blockDim.x + threadIdx.x;
    if (i < DM * DM)   g_wlin[i] = __uint_as_float(f2tf(Wlin[i]));
    if (i < DM * KMSG) g_wmsg[i] = __uint_as_float(f2tf(Wmsg[i]));
}

// ---------------------------------------------------------------------------
// Unified GEMM kernel (cp.async multistage, ldmatrix feeds, mma.sync tf32).
//  LEVEL=false: dst[r,:] = Aproj[r,:] @ Wlin^T          (proj)
//  LEVEL=true : row g: q=g>>4, j=g&15, s=j>>3, b=j&7, p=pbase+q, c=2p+1+s
//               A row g = concat(x[c], x[p], e[c-1]); C pairs (gid, gid+8)
//               share (q,b), differ in s -> min in-thread; write g_xs[p].
// BM==BN; WNW warps along N; NTHR/32 warps total.
// ---------------------------------------------------------------------------
template<int BM, int BN, int NTHR, int WNW, int STAGES, bool LEVEL>
__global__ __launch_bounds__(NTHR, (BM == 128 ? 2 : 3))
void gemm_k(const float* __restrict__ Aproj,   // proj: feats (unused for LEVEL)
            float* __restrict__ outBuf,        // proj: dst; LEVEL: x_parent/e (+child at top)
            int M, int K, int pbase, int childFromOut)
{
    constexpr int MW = (NTHR / 32) / WNW;        // warps along M
    constexpr int MT = BM / (16 * MW);           // 16-row mtiles per warp
    constexpr int NT = BN / (8 * WNW);           // 8-col ntiles per warp
    constexpr int STG_FLT = (BM + BN) * RS;      // floats per stage
    constexpr int TPR = NTHR / BM;               // loader threads per row
    constexpr int FPT = 32 / TPR;                // floats loaded per thread per row
    extern __shared__ float sm[];
    const uint32_t smBase = (uint32_t)__cvta_generic_to_shared(sm);

    const int tid = threadIdx.x, lane = tid & 31, wid = tid >> 5;
    const int gid = lane >> 2, tig = lane & 3;
    const int m0 = (wid / WNW) * (MT * 16);
    const int n0 = (wid % WNW) * (NT * 8);
    const int bn = blockIdx.x;
    const int rowBase = blockIdx.y * BM;

    // ldmatrix lane addressing
    const int laneRowA = (lane & 7) + (lane & 8);        // 0..15 pattern for x4
    const int colA4 = ((lane >> 4) & 1) * 4;             // +4 floats for lanes 16..31
    const int laneRowB = lane & 7;
    const int colB4 = ((lane >> 3) & 1) * 4;             // lanes 0..15 meaningful for x2

    const float* W = LEVEL ? g_wmsg : g_wlin;

    // ---- loader setup ----
    const int ra = tid / TPR;
    const int coff = (tid % TPR) * FPT;
    const float* asrc[3];
    if (LEVEL) {
        const float* childRO = childFromOut ? (const float*)outBuf : (const float*)g_xs;
        int g = min(rowBase + ra, M - 1);
        int q = g >> 4, j = g & 15, s = j >> 3, b = j & 7;
        int p = pbase + q, c = 2 * p + 1 + s;
        asrc[0] = childRO + (size_t)c * TOK + b * DM;                       // x[child]
        asrc[1] = outBuf + (size_t)p * TOK + b * DM;                        // x[parent]
        asrc[2] = outBuf + (size_t)(N_NODES + c - 1) * TOK + b * DM;        // e[child-1]
    } else {
        int g = min(rowBase + ra, M - 1);
        asrc[0] = asrc[1] = asrc[2] = Aproj + (size_t)g * DM;
    }
    const float* bsrc = W + (size_t)(bn * BN + ra) * K;

    const int nslab = K >> 5;

    auto load_stage = [&](int slab, int buf) {
        int kg = slab << 5;
        const float* a = asrc[kg >> 8] + (kg & 255) + coff;
        const float* b = bsrc + kg + coff;
        uint32_t da = smBase + (uint32_t)(buf * STG_FLT + ra * RS + coff) * 4u;
        uint32_t db = smBase + (uint32_t)(buf * STG_FLT + BM * RS + ra * RS + coff) * 4u;
#pragma unroll
        for (int i = 0; i < FPT / 4; i++) { cp16(da + i * 16, a + i * 4); cp16(db + i * 16, b + i * 4); }
        cp_commit();
    };

#pragma unroll
    for (int s = 0; s < STAGES - 1; s++) load_stage(s, s);

    float acc[MT][NT][4];
#pragma unroll
    for (int mt = 0; mt < MT; mt++)
#pragma unroll
        for (int nt = 0; nt < NT; nt++)
#pragma unroll
            for (int c = 0; c < 4; c++) acc[mt][nt][c] = 0.f;

    for (int s = 0; s < nslab; s++) {
        cp_wait<STAGES - 2>();
        __syncthreads();
        // Refill buffer (s-1)%STAGES: consumed in iter s-1, all warps are past it.
        int nx = s + STAGES - 1;
        if (nx < nslab) load_stage(nx, nx % STAGES);
        else cp_commit();

        const uint32_t stB = smBase + (uint32_t)((s % STAGES) * STG_FLT) * 4u;
        const uint32_t aBase = stB + (uint32_t)((m0 + laneRowA) * RS + colA4) * 4u;
        const uint32_t bBase = stB + (uint32_t)(BM * RS + (n0 + laneRowB) * RS + colB4) * 4u;
#pragma unroll
        for (int k8 = 0; k8 < 4; k8++) {
            const int kb = k8 * 8;
            uint32_t a[MT][4];
#pragma unroll
            for (int mt = 0; mt < MT; mt++)
                ldsm_x4(a[mt][0], a[mt][1], a[mt][2], a[mt][3],
                        aBase + (uint32_t)((mt * 16 * RS + kb) * 4));
            uint32_t b[NT][2];
#pragma unroll
            for (int nt = 0; nt < NT; nt++)
                ldsm_x2(b[nt][0], b[nt][1],
                        bBase + (uint32_t)((nt * 8 * RS + kb) * 4));
#pragma unroll
            for (int mt = 0; mt < MT; mt++)
#pragma unroll
                for (int nt = 0; nt < NT; nt++)
                    mma_tf32(acc[mt][nt][0], acc[mt][nt][1], acc[mt][nt][2], acc[mt][nt][3],
                             a[mt][0], a[mt][1], a[mt][2], a[mt][3], b[nt][0], b[nt][1]);
        }
    }

    // ---- epilogue ----
    if (!LEVEL) {
#pragma unroll
        for (int mt = 0; mt < MT; mt++) {
            int r = rowBase + m0 + mt * 16 + gid;
#pragma unroll
            for (int nt = 0; nt < NT; nt++) {
                int ncol = bn * BN + n0 + nt * 8 + 2 * tig;
                if (r < M)
                    *(float2*)(outBuf + (size_t)r * DM + ncol) =
                        make_float2(acc[mt][nt][0], acc[mt][nt][1]);
                if (r + 8 < M)
                    *(float2*)(outBuf + (size_t)(r + 8) * DM + ncol) =
                        make_float2(acc[mt][nt][2], acc[mt][nt][3]);
            }
        }
    } else {
#pragma unroll
        for (int mt = 0; mt < MT; mt++) {
            int r = rowBase + m0 + mt * 16 + gid;   // s=0 row (r&15 = gid < 8)
            if (r < M) {
                int p = pbase + (r >> 4), b = r & 7;
                float* o = g_xs + (size_t)p * TOK + b * DM + bn * BN + n0 + 2 * tig;
#pragma unroll
                for (int nt = 0; nt < NT; nt++)
                    *(float2*)(o + nt * 8) =
                        make_float2(fminf(acc[mt][nt][0], acc[mt][nt][2]),
                                    fminf(acc[mt][nt][1], acc[mt][nt][3]));
            }
        }
    }
}

// ---------------------------------------------------------------------------
// Final merge: internal-node x scratch -> d_out
// ---------------------------------------------------------------------------
__global__ __launch_bounds__(256) void merge_kernel(float* __restrict__ out)
{
    size_t idx = (size_t)blockIdx.x * blockDim.x + threadIdx.x;
    const size_t n4 = (size_t)N_INTERNAL * TOK / 4;
    if (idx < n4) ((float4*)out)[idx] = ((const float4*)g_xs)[idx];
}

// ---------------------------------------------------------------------------
#define SMEM_BIG   (3 * (128 + 128) * RS * 4)   // 110592 B
#define SMEM_SMALL (4 * (64 + 64) * RS * 4)     //  73728 B

// Big kernels: 256 threads, 8 warps of 64x32 (MT=4, NT=4), ldmatrix feeds.
// Small kernel: 128 threads, 4 warps of 32x32 over 64x64 tile (latency-bound levels).

extern "C" void kernel_launch(void* const* d_in, const int* in_sizes, int n_in,
                              void* d_out, int out_size)
{
    const float* feats = (const float*)d_in[0];
    const float* Wlin  = (const float*)d_in[1];
    const float* Wmsg  = (const float*)d_in[2];
    float* out = (float*)d_out;

    (void)cudaFuncSetAttribute((const void*)gemm_k<128, 128, 256, 4, 3, false>,
                               cudaFuncAttributeMaxDynamicSharedMemorySize, SMEM_BIG);
    (void)cudaFuncSetAttribute((const void*)gemm_k<128, 128, 256, 4, 3, true>,
                               cudaFuncAttributeMaxDynamicSharedMemorySize, SMEM_BIG);
    (void)cudaFuncSetAttribute((const void*)gemm_k<64, 64, 128, 2, 4, true>,
                               cudaFuncAttributeMaxDynamicSharedMemorySize, SMEM_SMALL);

    // 1) weights -> rna tf32
    prep_w_kernel<<<(DM * KMSG + 255) / 256, 256>>>(Wlin, Wmsg);

    // 2) projection: out = feats @ Wlin^T
    {
        dim3 grid(DM / 128, (MTOT + 127) / 128);   // (2, 1024)
        gemm_k<128, 128, 256, 4, 3, false><<<grid, 256, SMEM_BIG>>>(
            feats, out, MTOT, DM, 0, 0);
    }

    // 3) tree levels
    for (int d = TREE_DEPTH - 2; d >= 0; --d) {
        int pbase = (1 << d) - 1;
        int pcount = 1 << d;
        int M = pcount * 16;
        int cfo = (d == TREE_DEPTH - 2) ? 1 : 0;
        if (d >= 10) {
            dim3 grid(DM / 128, (M + 127) / 128);
            gemm_k<128, 128, 256, 4, 3, true><<<grid, 256, SMEM_BIG>>>(
                feats, out, M, KMSG, pbase, cfo);
        } else {
            dim3 grid(DM / 64, (M + 63) / 64);
            gemm_k<64, 64, 128, 2, 4, true><<<grid, 128, SMEM_SMALL>>>(
                feats, out, M, KMSG, pbase, cfo);
        }
    }

    // 4) merge internal-node x into d_out
    {
        size_t n4 = (size_t)N_INTERNAL * TOK / 4;
        merge_kernel<<<(int)((n4 + 255) / 256), 256>>>(out);
    }
}

// round 17
// speedup vs baseline: 1.4960x; 1.3078x over previous
#include <cuda_runtime.h>
#include <cstdint>

// ---------------------------------------------------------------------------
// Problem constants
// ---------------------------------------------------------------------------
#define TREE_DEPTH 13
#define N_NODES 8191
#define MAX_LEN 16381
#define DM 256
#define TOK 2048                  // 8 * 256 floats per token
#define N_INTERNAL 4095
#define RS 36                     // smem row stride in floats (bank-conflict-free)

// mega-GEMM regions (block-row ranges on grid.y)
#define RB0 256                   // internal tokens -> g_P  (W2L)
#define RB1 768                   // leaf+edge tokens -> out (Wlin)
#define RB2 512                   // edge tokens -> g_E     (W3L)
#define M0R 32760                 // 4095 * 8 rows
#define M1R 98288                 // 12286 * 8 rows
#define M2R 65520                 // 8190 * 8 rows
#define OFF1 32760                // feats row offset of leaf+edge region
#define OFF2 65528                // feats row offset of edge region

__device__ float g_xs[(size_t)N_INTERNAL * TOK];       // updated internal x (33.5 MB)
__device__ float g_P [(size_t)N_INTERNAL * TOK];       // parent term per internal node
__device__ float g_E [(size_t)(N_NODES - 1) * TOK];    // edge term per child (67 MB)
__device__ float g_wlin[DM * DM];                      // rna(Wlin)
__device__ float g_w1 [DM * DM];                       // rna(Wmsg[:,0:256])
__device__ float g_w2l[DM * DM];                       // rna(W2 @ Wlin)
__device__ float g_w3l[DM * DM];                       // rna(W3 @ Wlin)

// ---------------------------------------------------------------------------
// Helpers
// ---------------------------------------------------------------------------
__device__ __forceinline__ uint32_t f2tf(float x) {
    uint32_t r;
    asm("cvt.rna.tf32.f32 %0, %1;" : "=r"(r) : "f"(x));
    return r;
}
__device__ __forceinline__ void cp16(uint32_t dst, const void* src) {
    asm volatile("cp.async.cg.shared.global [%0], [%1], 16;" :: "r"(dst), "l"(src) : "memory");
}
__device__ __forceinline__ void cp_commit() {
    asm volatile("cp.async.commit_group;" ::: "memory");
}
template<int N> __device__ __forceinline__ void cp_wait() {
    asm volatile("cp.async.wait_group %0;" :: "n"(N) : "memory");
}
__device__ __forceinline__ void ldsm_x4(uint32_t& r0, uint32_t& r1, uint32_t& r2, uint32_t& r3,
                                        uint32_t addr) {
    asm volatile("ldmatrix.sync.aligned.m8n8.x4.shared.b16 {%0,%1,%2,%3}, [%4];"
                 : "=r"(r0), "=r"(r1), "=r"(r2), "=r"(r3) : "r"(addr));
}
__device__ __forceinline__ void ldsm_x2(uint32_t& r0, uint32_t& r1, uint32_t addr) {
    asm volatile("ldmatrix.sync.aligned.m8n8.x2.shared.b16 {%0,%1}, [%2];"
                 : "=r"(r0), "=r"(r1) : "r"(addr));
}
__device__ __forceinline__ void mma_tf32(float& c0, float& c1, float& c2, float& c3,
                                         uint32_t a0, uint32_t a1, uint32_t a2, uint32_t a3,
                                         uint32_t b0, uint32_t b1) {
    asm volatile(
        "mma.sync.aligned.m16n8k8.row.col.f32.tf32.tf32.f32 "
        "{%0,%1,%2,%3}, {%4,%5,%6,%7}, {%8,%9}, {%0,%1,%2,%3};"
        : "+f"(c0), "+f"(c1), "+f"(c2), "+f"(c3)
        : "r"(a0), "r"(a1), "r"(a2), "r"(a3), "r"(b0), "r"(b1));
}

// ---------------------------------------------------------------------------
// Weight prep: rna copies of Wlin and W1
// ---------------------------------------------------------------------------
__global__ void prep_w(const float* __restrict__ Wlin, const float* __restrict__ Wmsg)
{
    int i = blockIdx.x * 256 + threadIdx.x;
    if (i < DM * DM) {
        g_wlin[i] = __uint_as_float(f2tf(Wlin[i]));
        int n = i >> 8, k = i & 255;
        g_w1[i] = __uint_as_float(f2tf(Wmsg[(size_t)n * 768 + k]));
    }
}

// Weight products: W2L = W2 @ Wlin, W3L = W3 @ Wlin (fp32, then rna)
__global__ void prep_wl(const float* __restrict__ Wlin, const float* __restrict__ Wmsg)
{
    __shared__ float Wt[64][65];
    __shared__ float Lt[64][65];
    const int which = blockIdx.y;                // 0 = W2L, 1 = W3L
    const int n0 = (blockIdx.x >> 2) * 64;
    const int k0 = (blockIdx.x & 3) * 64;
    const int tx = threadIdx.x & 15, ty = threadIdx.x >> 4;
    const int wcol = which ? 512 : 256;
    float c[4][4] = {};
    for (int kt = 0; kt < 256; kt += 64) {
        for (int l = threadIdx.x; l < 64 * 64; l += 256) {
            int r = l >> 6, cc = l & 63;
            Wt[r][cc] = Wmsg[(size_t)(n0 + r) * 768 + wcol + kt + cc];
            Lt[r][cc] = Wlin[(size_t)(kt + r) * 256 + k0 + cc];
        }
        __syncthreads();
        for (int j = 0; j < 64; j++) {
            float wv[4], lv[4];
#pragma unroll
            for (int a = 0; a < 4; a++) { wv[a] = Wt[ty * 4 + a][j]; lv[a] = Lt[j][tx * 4 + a]; }
#pragma unroll
            for (int a = 0; a < 4; a++)
#pragma unroll
                for (int b = 0; b < 4; b++) c[a][b] += wv[a] * lv[b];
        }
        __syncthreads();
    }
    float* dst = which ? g_w3l : g_w2l;
#pragma unroll
    for (int a = 0; a < 4; a++)
#pragma unroll
        for (int b = 0; b < 4; b++)
            dst[(size_t)(n0 + ty * 4 + a) * 256 + k0 + tx * 4 + b] =
                __uint_as_float(f2tf(c[a][b]));
}

// ---------------------------------------------------------------------------
// Mega GEMM: K=256, three regions by grid.y:
//   [0,RB0)         : g_P[r]  = feats[r]        @ W2L^T
//   [RB0,RB0+RB1)   : out[r'] = feats[r'=OFF1+r] @ Wlin^T   (leaf x + e outputs)
//   [RB0+RB1, ...)  : g_E[r]  = feats[OFF2+r]   @ W3L^T
// ---------------------------------------------------------------------------
#define STAGES 3
#define STG_FLT ((128 + 128) * RS)
#define SMEM_BIG   (STAGES * STG_FLT * 4)       // 110592 B
#define SMEM_SMALL (STAGES * (64 + 64) * RS * 4) // 55296 B

__global__ __launch_bounds__(256, 2)
void mega_k(const float* __restrict__ feats, float* __restrict__ out)
{
    constexpr int MT = 4, NT = 4;
    extern __shared__ float sm[];
    const uint32_t smBase = (uint32_t)__cvta_generic_to_shared(sm);

    const int tid = threadIdx.x, lane = tid & 31, wid = tid >> 5;
    const int gid = lane >> 2, tig = lane & 3;
    const int m0 = (wid >> 2) * 64;
    const int n0 = (wid & 3) * 32;
    const int bn = blockIdx.x;
    const int by = blockIdx.y;

    int region, blockRow;
    if (by < RB0)            { region = 0; blockRow = by; }
    else if (by < RB0 + RB1) { region = 1; blockRow = by - RB0; }
    else                     { region = 2; blockRow = by - RB0 - RB1; }
    const int Mreg  = region == 0 ? M0R : (region == 1 ? M1R : M2R);
    const int rowOff = region == 0 ? 0 : (region == 1 ? OFF1 : OFF2);
    const float* W = region == 0 ? g_w2l : (region == 1 ? g_wlin : g_w3l);
    const int rowBase = blockRow * 128;

    const int laneRowA = (lane & 7) + (lane & 8);
    const int colA4 = ((lane >> 4) & 1) * 4;
    const int laneRowB = lane & 7;
    const int colB4 = ((lane >> 3) & 1) * 4;

    const int ra = tid >> 1;
    const int coff = (tid & 1) * 16;
    const float* asrc = feats + (size_t)(rowOff + min(rowBase + ra, Mreg - 1)) * DM;
    const float* bsrc = W + (size_t)(bn * 128 + ra) * DM;

    auto load_stage = [&](int slab, int buf) {
        int kg = slab << 5;
        const float* a = asrc + kg + coff;
        const float* b = bsrc + kg + coff;
        uint32_t da = smBase + (uint32_t)(buf * STG_FLT + ra * RS + coff) * 4u;
        uint32_t db = smBase + (uint32_t)(buf * STG_FLT + 128 * RS + ra * RS + coff) * 4u;
#pragma unroll
        for (int i = 0; i < 4; i++) { cp16(da + i * 16, a + i * 4); cp16(db + i * 16, b + i * 4); }
        cp_commit();
    };

#pragma unroll
    for (int s = 0; s < STAGES - 1; s++) load_stage(s, s);

    float acc[MT][NT][4];
#pragma unroll
    for (int mt = 0; mt < MT; mt++)
#pragma unroll
        for (int nt = 0; nt < NT; nt++)
#pragma unroll
            for (int c = 0; c < 4; c++) acc[mt][nt][c] = 0.f;

    const int nslab = 8;
    for (int s = 0; s < nslab; s++) {
        cp_wait<STAGES - 2>();
        __syncthreads();
        int nx = s + STAGES - 1;
        if (nx < nslab) load_stage(nx, nx % STAGES);
        else cp_commit();

        const uint32_t stB = smBase + (uint32_t)((s % STAGES) * STG_FLT) * 4u;
        const uint32_t aBase = stB + (uint32_t)((m0 + laneRowA) * RS + colA4) * 4u;
        const uint32_t bBase = stB + (uint32_t)(128 * RS + (n0 + laneRowB) * RS + colB4) * 4u;
#pragma unroll
        for (int k8 = 0; k8 < 4; k8++) {
            const int kb = k8 * 8;
            uint32_t a[MT][4];
#pragma unroll
            for (int mt = 0; mt < MT; mt++)
                ldsm_x4(a[mt][0], a[mt][1], a[mt][2], a[mt][3],
                        aBase + (uint32_t)((mt * 16 * RS + kb) * 4));
            uint32_t b[NT][2];
#pragma unroll
            for (int nt = 0; nt < NT; nt++)
                ldsm_x2(b[nt][0], b[nt][1], bBase + (uint32_t)((nt * 8 * RS + kb) * 4));
#pragma unroll
            for (int mt = 0; mt < MT; mt++)
#pragma unroll
                for (int nt = 0; nt < NT; nt++)
                    mma_tf32(acc[mt][nt][0], acc[mt][nt][1], acc[mt][nt][2], acc[mt][nt][3],
                             a[mt][0], a[mt][1], a[mt][2], a[mt][3], b[nt][0], b[nt][1]);
        }
    }

    float* dst0 = region == 0 ? g_P : (region == 1 ? out : g_E);
    const int dstAdd = region == 1 ? OFF1 : 0;
#pragma unroll
    for (int mt = 0; mt < MT; mt++) {
        int r = rowBase + m0 + mt * 16 + gid;
#pragma unroll
        for (int nt = 0; nt < NT; nt++) {
            int ncol = bn * 128 + n0 + nt * 8 + 2 * tig;
            if (r < Mreg)
                *(float2*)(dst0 + (size_t)(dstAdd + r) * DM + ncol) =
                    make_float2(acc[mt][nt][0], acc[mt][nt][1]);
            if (r + 8 < Mreg)
                *(float2*)(dst0 + (size_t)(dstAdd + r + 8) * DM + ncol) =
                    make_float2(acc[mt][nt][2], acc[mt][nt][3]);
        }
    }
}

// ---------------------------------------------------------------------------
// Level kernel (K=256): row g: q=g>>4, j=g&15, s=j>>3, b=j&7, p=pbase+q,
// c=2p+1+s. A row = x[c]; acc init = P[p] + E[c-1]; W = W1.
// C pairs (gid, gid+8) share (q,b), differ in s -> min in-thread; write g_xs[p].
// ---------------------------------------------------------------------------
template<int BM, int NTHR, int WNW>
__global__ __launch_bounds__(NTHR, (BM == 128 ? 2 : 4))
void level_k(const float* __restrict__ outBuf, int M, int pbase, int childFromOut)
{
    constexpr int MW = (NTHR / 32) / WNW;
    constexpr int MT = BM / (16 * MW);
    constexpr int NT = BM / (8 * WNW);
    constexpr int SF = (BM + BM) * RS;
    constexpr int TPR = NTHR / BM;
    constexpr int FPT = 32 / TPR;
    extern __shared__ float sm[];
    const uint32_t smBase = (uint32_t)__cvta_generic_to_shared(sm);

    const int tid = threadIdx.x, lane = tid & 31, wid = tid >> 5;
    const int gid = lane >> 2, tig = lane & 3;
    const int m0 = (wid / WNW) * (MT * 16);
    const int n0 = (wid % WNW) * (NT * 8);
    const int bn = blockIdx.x;
    const int rowBase = blockIdx.y * BM;

    const int laneRowA = (lane & 7) + (lane & 8);
    const int colA4 = ((lane >> 4) & 1) * 4;
    const int laneRowB = lane & 7;
    const int colB4 = ((lane >> 3) & 1) * 4;

    const float* childRO = childFromOut ? outBuf : (const float*)g_xs;

    const int ra = tid / TPR;
    const int coff = (tid % TPR) * FPT;
    const float* asrc;
    {
        int g = min(rowBase + ra, M - 1);
        int q = g >> 4, j = g & 15, s = j >> 3, b = j & 7;
        int p = pbase + q, c = 2 * p + 1 + s;
        asrc = childRO + (size_t)c * TOK + b * DM;
    }
    const float* bsrc = g_w1 + (size_t)(bn * BM + ra) * DM;

    auto load_stage = [&](int slab, int buf) {
        int kg = slab << 5;
        const float* a = asrc + kg + coff;
        const float* b = bsrc + kg + coff;
        uint32_t da = smBase + (uint32_t)(buf * SF + ra * RS + coff) * 4u;
        uint32_t db = smBase + (uint32_t)(buf * SF + BM * RS + ra * RS + coff) * 4u;
#pragma unroll
        for (int i = 0; i < FPT / 4; i++) { cp16(da + i * 16, a + i * 4); cp16(db + i * 16, b + i * 4); }
        cp_commit();
    };

#pragma unroll
    for (int s = 0; s < STAGES - 1; s++) load_stage(s, s);

    // acc init from P[parent] + E[child-1]
    float acc[MT][NT][4];
#pragma unroll
    for (int mt = 0; mt < MT; mt++) {
        int r = rowBase + m0 + mt * 16 + gid;      // s=0 row
        bool v = (r < M);
        int rc = v ? r : 0;
        int p = pbase + (rc >> 4), b = rc & 7;
        int col = bn * BM + n0 + 2 * tig;
        const float* Pp = g_P + ((size_t)p * 8 + b) * DM + col;
        const float* E0 = g_E + ((size_t)(2 * p) * 8 + b) * DM + col;
        const float* E1 = g_E + ((size_t)(2 * p + 1) * 8 + b) * DM + col;
#pragma unroll
        for (int nt = 0; nt < NT; nt++) {
            if (v) {
                float2 Pv = *(const float2*)(Pp + nt * 8);
                float2 e0 = *(const float2*)(E0 + nt * 8);
                float2 e1 = *(const float2*)(E1 + nt * 8);
                acc[mt][nt][0] = Pv.x + e0.x; acc[mt][nt][1] = Pv.y + e0.y;
                acc[mt][nt][2] = Pv.x + e1.x; acc[mt][nt][3] = Pv.y + e1.y;
            } else {
                acc[mt][nt][0] = acc[mt][nt][1] = acc[mt][nt][2] = acc[mt][nt][3] = 0.f;
            }
        }
    }

    const int nslab = 8;
    for (int s = 0; s < nslab; s++) {
        cp_wait<STAGES - 2>();
        __syncthreads();
        int nx = s + STAGES - 1;
        if (nx < nslab) load_stage(nx, nx % STAGES);
        else cp_commit();

        const uint32_t stB = smBase + (uint32_t)((s % STAGES) * SF) * 4u;
        const uint32_t aBase = stB + (uint32_t)((m0 + laneRowA) * RS + colA4) * 4u;
        const uint32_t bBase = stB + (uint32_t)(BM * RS + (n0 + laneRowB) * RS + colB4) * 4u;
#pragma unroll
        for (int k8 = 0; k8 < 4; k8++) {
            const int kb = k8 * 8;
            uint32_t a[MT][4];
#pragma unroll
            for (int mt = 0; mt < MT; mt++)
                ldsm_x4(a[mt][0], a[mt][1], a[mt][2], a[mt][3],
                        aBase + (uint32_t)((mt * 16 * RS + kb) * 4));
            uint32_t b[NT][2];
#pragma unroll
            for (int nt = 0; nt < NT; nt++)
                ldsm_x2(b[nt][0], b[nt][1], bBase + (uint32_t)((nt * 8 * RS + kb) * 4));
#pragma unroll
            for (int mt = 0; mt < MT; mt++)
#pragma unroll
                for (int nt = 0; nt < NT; nt++)
                    mma_tf32(acc[mt][nt][0], acc[mt][nt][1], acc[mt][nt][2], acc[mt][nt][3],
                             a[mt][0], a[mt][1], a[mt][2], a[mt][3], b[nt][0], b[nt][1]);
        }
    }

    // epilogue: min over s, write x_new[p]
#pragma unroll
    for (int mt = 0; mt < MT; mt++) {
        int r = rowBase + m0 + mt * 16 + gid;
        if (r < M) {
            int p = pbase + (r >> 4), b = r & 7;
            float* o = g_xs + (size_t)p * TOK + b * DM + bn * BM + n0 + 2 * tig;
#pragma unroll
            for (int nt = 0; nt < NT; nt++)
                *(float2*)(o + nt * 8) =
                    make_float2(fminf(acc[mt][nt][0], acc[mt][nt][2]),
                                fminf(acc[mt][nt][1], acc[mt][nt][3]));
        }
    }
}

// ---------------------------------------------------------------------------
// Final merge: internal-node x scratch -> d_out rows [0, 32760)
// ---------------------------------------------------------------------------
__global__ __launch_bounds__(256) void merge_kernel(float* __restrict__ out)
{
    size_t idx = (size_t)blockIdx.x * blockDim.x + threadIdx.x;
    const size_t n4 = (size_t)N_INTERNAL * TOK / 4;
    if (idx < n4) ((float4*)out)[idx] = ((const float4*)g_xs)[idx];
}

// ---------------------------------------------------------------------------
extern "C" void kernel_launch(void* const* d_in, const int* in_sizes, int n_in,
                              void* d_out, int out_size)
{
    const float* feats = (const float*)d_in[0];
    const float* Wlin  = (const float*)d_in[1];
    const float* Wmsg  = (const float*)d_in[2];
    float* out = (float*)d_out;

    (void)cudaFuncSetAttribute((const void*)mega_k,
                               cudaFuncAttributeMaxDynamicSharedMemorySize, SMEM_BIG);
    (void)cudaFuncSetAttribute((const void*)level_k<128, 256, 4>,
                               cudaFuncAttributeMaxDynamicSharedMemorySize, SMEM_BIG);
    (void)cudaFuncSetAttribute((const void*)level_k<64, 128, 2>,
                               cudaFuncAttributeMaxDynamicSharedMemorySize, SMEM_SMALL);

    // 1) weight preps
    prep_w<<<256, 256>>>(Wlin, Wmsg);
    prep_wl<<<dim3(16, 2), 256>>>(Wlin, Wmsg);

    // 2) mega GEMM: P (internal), proj (leaf+edge), E (edges)
    mega_k<<<dim3(2, RB0 + RB1 + RB2), 256, SMEM_BIG>>>(feats, out);

    // 3) tree levels, K=256 each
    for (int d = TREE_DEPTH - 2; d >= 0; --d) {
        int pbase = (1 << d) - 1;
        int pcount = 1 << d;
        int M = pcount * 16;
        int cfo = (d == TREE_DEPTH - 2) ? 1 : 0;
        if (d >= 10) {
            dim3 grid(2, (M + 127) / 128);
            level_k<128, 256, 4><<<grid, 256, SMEM_BIG>>>(out, M, pbase, cfo);
        } else {
            dim3 grid(4, (M + 63) / 64);
            level_k<64, 128, 2><<<grid, 128, SMEM_SMALL>>>(out, M, pbase, cfo);
        }
    }

    // 4) merge internal-node x into d_out
    {
        size_t n4 = (size_t)N_INTERNAL * TOK / 4;
        merge_kernel<<<(int)((n4 + 255) / 256), 256>>>(out);
    }
}